// round 1
// baseline (speedup 1.0000x reference)
#include <cuda_runtime.h>
#include <math.h>

// Chamfer distance, B=4, N=M=8192, 3D.
// Outputs packed into d_out (float32): dist1[B*N] | dist2[B*M] | idx1[B*N] | idx2[B*M]
// Indices written as float(idx) (exactly representable, <= 8191).

#define QPB 128   // queries per block (= blockDim.x)
#define CH 1024   // candidate chunk staged in shared memory

__global__ __launch_bounds__(QPB) void chamfer_kernel(
    const float* __restrict__ xyz1,
    const float* __restrict__ xyz2,
    float* __restrict__ out,   // base of d_out
    int N, int M)
{
    __shared__ float sx[CH];
    __shared__ float sy[CH];
    __shared__ float sz[CH];

    const int dir = blockIdx.z;          // 0: xyz1->xyz2, 1: xyz2->xyz1
    const int b   = blockIdx.y;

    const float* q;   // query points
    const float* c;   // candidate points
    float* outd;
    float* outi;
    int Nq, Nc;
    if (dir == 0) {
        q = xyz1; c = xyz2; Nq = N; Nc = M;
        outd = out;                         // dist1
        outi = out + (size_t)N*4 + (size_t)M*4;  // idx1 (after dist1, dist2)
    } else {
        q = xyz2; c = xyz1; Nq = M; Nc = N;
        outd = out + (size_t)N*4;           // dist2
        outi = out + (size_t)N*4 + (size_t)M*4 + (size_t)N*4; // idx2
    }

    const int qi = blockIdx.x * QPB + threadIdx.x;
    const float* qb = q + ((size_t)b * Nq + qi) * 3;
    const float* cb = c + (size_t)b * Nc * 3;

    const float px = qb[0];
    const float py = qb[1];
    const float pz = qb[2];

    float best = INFINITY;
    int   bi   = 0;

    for (int base = 0; base < Nc; base += CH) {
        __syncthreads();
        // Stage CH candidate points into SoA shared arrays (coalesced GMEM reads).
        for (int t = threadIdx.x; t < CH; t += QPB) {
            const float* p = cb + (size_t)(base + t) * 3;
            sx[t] = p[0];
            sy[t] = p[1];
            sz[t] = p[2];
        }
        __syncthreads();

        #pragma unroll 8
        for (int j = 0; j < CH; ++j) {
            // Match XLA's non-contracted fp32 evaluation exactly:
            // d = ((dx*dx) + (dy*dy)) + (dz*dz), each op round-to-nearest, NO FMA.
            float dx = __fsub_rn(px, sx[j]);
            float dy = __fsub_rn(py, sy[j]);
            float dz = __fsub_rn(pz, sz[j]);
            float d  = __fadd_rn(__fadd_rn(__fmul_rn(dx, dx), __fmul_rn(dy, dy)),
                                 __fmul_rn(dz, dz));
            // Strict < with ascending j == first-occurrence argmin (matches jnp.argmin
            // and the reference's chunked `dc < best_d2` update).
            if (d < best) { best = d; bi = base + j; }
        }
    }

    outd[(size_t)b * Nq + qi] = best;
    outi[(size_t)b * Nq + qi] = (float)bi;
}

extern "C" void kernel_launch(void* const* d_in, const int* in_sizes, int n_in,
                              void* d_out, int out_size)
{
    const float* xyz1 = (const float*)d_in[0];  // [4, 8192, 3]
    const float* xyz2 = (const float*)d_in[1];  // [4, 8192, 3]
    float* out = (float*)d_out;

    const int B = 4;
    const int N = in_sizes[0] / (B * 3);  // 8192
    const int M = in_sizes[1] / (B * 3);  // 8192

    dim3 block(QPB, 1, 1);
    dim3 grid(N / QPB, B, 2);  // z: direction (N==M so same tiling)
    chamfer_kernel<<<grid, block>>>(xyz1, xyz2, out, N, M);
}

// round 2
// speedup vs baseline: 1.7834x; 1.7834x over previous
#include <cuda_runtime.h>
#include <math.h>

// Chamfer distance, B=4, N=M=8192, 3D.
// d_out (float32): dist1[B*N] | dist2[B*M] | idx1[B*N] | idx2[B*M]
// Strategy: issue-rate bound -> minimize instructions/candidate.
//  - packed f32x2 add/mul (2 candidates per fp instruction, exact per-lane rn rounding)
//  - candidates staged NEGATED in smem so subtract == packed add (exact)
//  - FMNMX min-tree per 8-candidate group, index recovered in a rare branch arm
//  - lowest-index-wins ties everywhere (matches jnp.argmin / chunked `<` update)

#define QPB 64    // threads per block (queries per block)
#define CH 1024   // candidate chunk staged in shared memory

typedef unsigned long long u64;

__device__ __forceinline__ u64 pack2(float lo, float hi) {
    u64 r;
    asm("mov.b64 %0, {%1, %2};" : "=l"(r) : "f"(lo), "f"(hi));
    return r;
}
__device__ __forceinline__ void unpack2(float& lo, float& hi, u64 v) {
    asm("mov.b64 {%0, %1}, %2;" : "=f"(lo), "=f"(hi) : "l"(v));
}
__device__ __forceinline__ u64 add2(u64 a, u64 b) {
    u64 r;
    asm("add.rn.f32x2 %0, %1, %2;" : "=l"(r) : "l"(a), "l"(b));
    return r;
}
__device__ __forceinline__ u64 mul2(u64 a, u64 b) {
    u64 r;
    asm("mul.rn.f32x2 %0, %1, %2;" : "=l"(r) : "l"(a), "l"(b));
    return r;
}

__global__ __launch_bounds__(QPB) void chamfer_kernel(
    const float* __restrict__ xyz1,
    const float* __restrict__ xyz2,
    float* __restrict__ out,
    int N, int M, int B)
{
    // SoA staged candidate coords (negated), viewed as float4 for LDS.128.
    __shared__ float4 s4[3 * CH / 4];
    float4* sx4 = s4;
    float4* sy4 = s4 + CH / 4;
    float4* sz4 = s4 + 2 * (CH / 4);
    float* sx = (float*)sx4;
    float* sy = (float*)sy4;
    float* sz = (float*)sz4;

    const int dir = blockIdx.z;   // 0: xyz1->xyz2, 1: xyz2->xyz1
    const int b   = blockIdx.y;

    const float* q; const float* c;
    float* outd; float* outi;
    int Nq, Nc;
    if (dir == 0) {
        q = xyz1; c = xyz2; Nq = N; Nc = M;
        outd = out;                                          // dist1
        outi = out + (size_t)B * N + (size_t)B * M;          // idx1
    } else {
        q = xyz2; c = xyz1; Nq = M; Nc = N;
        outd = out + (size_t)B * N;                          // dist2
        outi = out + (size_t)B * N + (size_t)B * M + (size_t)B * N; // idx2
    }

    const int qi = blockIdx.x * QPB + threadIdx.x;
    const float* qb = q + ((size_t)b * Nq + qi) * 3;
    const float* cb = c + (size_t)b * Nc * 3;

    const float px = qb[0];
    const float py = qb[1];
    const float pz = qb[2];
    const u64 pxx = pack2(px, px);
    const u64 pyy = pack2(py, py);
    const u64 pzz = pack2(pz, pz);

    float best = INFINITY;
    int   bi   = 0;

    for (int base = 0; base < Nc; base += CH) {
        __syncthreads();
        // Stage CH candidates, NEGATED, into SoA smem.
        for (int t = threadIdx.x; t < CH; t += QPB) {
            const float* p = cb + (size_t)(base + t) * 3;
            sx[t] = -p[0];
            sy[t] = -p[1];
            sz[t] = -p[2];
        }
        __syncthreads();

        #pragma unroll 2
        for (int g = 0; g < CH / 8; ++g) {
            const float4 X0 = sx4[2 * g], X1 = sx4[2 * g + 1];
            const float4 Y0 = sy4[2 * g], Y1 = sy4[2 * g + 1];
            const float4 Z0 = sz4[2 * g], Z1 = sz4[2 * g + 1];

            // dx = px + (-cx): exact same rounding as px - cx, 2 lanes/instr.
            u64 dx01 = add2(pxx, pack2(X0.x, X0.y));
            u64 dx23 = add2(pxx, pack2(X0.z, X0.w));
            u64 dx45 = add2(pxx, pack2(X1.x, X1.y));
            u64 dx67 = add2(pxx, pack2(X1.z, X1.w));
            u64 dy01 = add2(pyy, pack2(Y0.x, Y0.y));
            u64 dy23 = add2(pyy, pack2(Y0.z, Y0.w));
            u64 dy45 = add2(pyy, pack2(Y1.x, Y1.y));
            u64 dy67 = add2(pyy, pack2(Y1.z, Y1.w));
            u64 dz01 = add2(pzz, pack2(Z0.x, Z0.y));
            u64 dz23 = add2(pzz, pack2(Z0.z, Z0.w));
            u64 dz45 = add2(pzz, pack2(Z1.x, Z1.y));
            u64 dz67 = add2(pzz, pack2(Z1.z, Z1.w));

            // ((dx*dx + dy*dy) + dz*dz), each op rn-rounded, NO FMA: matches XLA.
            u64 d01 = add2(add2(mul2(dx01, dx01), mul2(dy01, dy01)), mul2(dz01, dz01));
            u64 d23 = add2(add2(mul2(dx23, dx23), mul2(dy23, dy23)), mul2(dz23, dz23));
            u64 d45 = add2(add2(mul2(dx45, dx45), mul2(dy45, dy45)), mul2(dz45, dz45));
            u64 d67 = add2(add2(mul2(dx67, dx67), mul2(dy67, dy67)), mul2(dz67, dz67));

            float d0, d1, d2, d3, d4, d5, d6, d7;
            unpack2(d0, d1, d01);
            unpack2(d2, d3, d23);
            unpack2(d4, d5, d45);
            unpack2(d6, d7, d67);

            const float m = fminf(fminf(fminf(d0, d1), fminf(d2, d3)),
                                  fminf(fminf(d4, d5), fminf(d6, d7)));

            if (m < best) {   // strict <: earlier groups win ties
                best = m;
                const int jb = base + g * 8;
                // First-occurrence argmin within the group: descending scan,
                // last write (lowest k with d[k]==m) wins. m is bit-exact one of d[k].
                int s = jb + 7;
                if (d6 == m) s = jb + 6;
                if (d5 == m) s = jb + 5;
                if (d4 == m) s = jb + 4;
                if (d3 == m) s = jb + 3;
                if (d2 == m) s = jb + 2;
                if (d1 == m) s = jb + 1;
                if (d0 == m) s = jb;
                bi = s;
            }
        }
    }

    outd[(size_t)b * Nq + qi] = best;
    outi[(size_t)b * Nq + qi] = (float)bi;   // <= 8191, exact in fp32
}

extern "C" void kernel_launch(void* const* d_in, const int* in_sizes, int n_in,
                              void* d_out, int out_size)
{
    const float* xyz1 = (const float*)d_in[0];  // [4, 8192, 3]
    const float* xyz2 = (const float*)d_in[1];  // [4, 8192, 3]
    float* out = (float*)d_out;

    const int B = 4;
    const int N = in_sizes[0] / (B * 3);  // 8192
    const int M = in_sizes[1] / (B * 3);  // 8192

    dim3 block(QPB, 1, 1);
    dim3 grid(N / QPB, B, 2);   // 1024 blocks: fine-grained, balanced across 148 SMs
    chamfer_kernel<<<grid, block>>>(xyz1, xyz2, out, N, M, B);
}

// round 3
// speedup vs baseline: 2.0329x; 1.1399x over previous
#include <cuda_runtime.h>
#include <math.h>

// Chamfer distance, B=4, N=M=8192, 3D.
// d_out (float32): dist1[B*N] | dist2[B*M] | idx1[B*N] | idx2[B*M]
// Issue/latency optimized:
//  - packed f32x2 add/mul (2 candidates per fp instruction, exact per-lane rn)
//  - candidates staged NEGATED in smem; LDS.128 as ulonglong2 -> f32x2 operands
//    with zero pack MOVs
//  - 2 segment-threads per query (candidate split) -> 2x occupancy; exact
//    min-index tie-break in the combine
//  - FMNMX min-tree per 8-group (alu pipe), index recovery in rare branch arm

#define QPB 128            // 64 queries x 2 segments
#define NQ_BLK 64
#define CH 1024            // candidates staged per chunk
#define SEG 512            // candidates per segment per chunk

typedef unsigned long long u64;

__device__ __forceinline__ void unpack2(float& lo, float& hi, u64 v) {
    asm("mov.b64 {%0, %1}, %2;" : "=f"(lo), "=f"(hi) : "l"(v));
}
__device__ __forceinline__ u64 pack2(float lo, float hi) {
    u64 r;
    asm("mov.b64 %0, {%1, %2};" : "=l"(r) : "f"(lo), "f"(hi));
    return r;
}
__device__ __forceinline__ u64 add2(u64 a, u64 b) {
    u64 r;
    asm("add.rn.f32x2 %0, %1, %2;" : "=l"(r) : "l"(a), "l"(b));
    return r;
}
__device__ __forceinline__ u64 mul2(u64 a, u64 b) {
    u64 r;
    asm("mul.rn.f32x2 %0, %1, %2;" : "=l"(r) : "l"(a), "l"(b));
    return r;
}

__global__ __launch_bounds__(QPB) void chamfer_kernel(
    const float* __restrict__ xyz1,
    const float* __restrict__ xyz2,
    float* __restrict__ out,
    int N, int M, int B)
{
    __shared__ __align__(16) float smem_f[3 * CH];   // negated SoA: x | y | z
    __shared__ float rbest[QPB];
    __shared__ int   rbi[QPB];

    float* sx = smem_f;
    float* sy = smem_f + CH;
    float* sz = smem_f + 2 * CH;

    const int dir = blockIdx.z;   // 0: xyz1->xyz2, 1: xyz2->xyz1
    const int b   = blockIdx.y;

    const float* q; const float* c;
    float* outd; float* outi;
    int Nq, Nc;
    if (dir == 0) {
        q = xyz1; c = xyz2; Nq = N; Nc = M;
        outd = out;
        outi = out + (size_t)B * N + (size_t)B * M;
    } else {
        q = xyz2; c = xyz1; Nq = M; Nc = N;
        outd = out + (size_t)B * N;
        outi = out + (size_t)B * N + (size_t)B * M + (size_t)B * N;
    }

    const int tid  = threadIdx.x;
    const int ql   = tid & (NQ_BLK - 1);     // query lane within block
    const int seg  = tid >> 6;               // 0 or 1: candidate segment
    const int qi   = blockIdx.x * NQ_BLK + ql;

    const float* qb = q + ((size_t)b * Nq + qi) * 3;
    const float* cb = c + (size_t)b * Nc * 3;

    const float px = qb[0];
    const float py = qb[1];
    const float pz = qb[2];
    const u64 pxx = pack2(px, px);
    const u64 pyy = pack2(py, py);
    const u64 pzz = pack2(pz, pz);

    // Segment views of the staged chunk (64-bit lanes, 16B vectors).
    const ulonglong2* sxv = (const ulonglong2*)(sx + seg * SEG);
    const ulonglong2* syv = (const ulonglong2*)(sy + seg * SEG);
    const ulonglong2* szv = (const ulonglong2*)(sz + seg * SEG);

    float best = INFINITY;
    int   bi   = 0;

    for (int base = 0; base < Nc; base += CH) {
        __syncthreads();
        // Stage CH candidates, NEGATED, into SoA smem (all 128 threads).
        for (int t = tid; t < CH; t += QPB) {
            const float* p = cb + (size_t)(base + t) * 3;
            sx[t] = -p[0];
            sy[t] = -p[1];
            sz[t] = -p[2];
        }
        __syncthreads();

        const int segbase = base + seg * SEG;

        #pragma unroll 4
        for (int g = 0; g < SEG / 8; ++g) {
            const ulonglong2 X0 = sxv[2 * g], X1 = sxv[2 * g + 1];
            const ulonglong2 Y0 = syv[2 * g], Y1 = syv[2 * g + 1];
            const ulonglong2 Z0 = szv[2 * g], Z1 = szv[2 * g + 1];

            // dx = px + (-cx): identical rounding to px - cx.
            u64 dx01 = add2(pxx, X0.x);
            u64 dx23 = add2(pxx, X0.y);
            u64 dx45 = add2(pxx, X1.x);
            u64 dx67 = add2(pxx, X1.y);
            u64 dy01 = add2(pyy, Y0.x);
            u64 dy23 = add2(pyy, Y0.y);
            u64 dy45 = add2(pyy, Y1.x);
            u64 dy67 = add2(pyy, Y1.y);
            u64 dz01 = add2(pzz, Z0.x);
            u64 dz23 = add2(pzz, Z0.y);
            u64 dz45 = add2(pzz, Z1.x);
            u64 dz67 = add2(pzz, Z1.y);

            // ((dx*dx + dy*dy) + dz*dz), each op rn-rounded, NO FMA (matches XLA).
            u64 d01 = add2(add2(mul2(dx01, dx01), mul2(dy01, dy01)), mul2(dz01, dz01));
            u64 d23 = add2(add2(mul2(dx23, dx23), mul2(dy23, dy23)), mul2(dz23, dz23));
            u64 d45 = add2(add2(mul2(dx45, dx45), mul2(dy45, dy45)), mul2(dz45, dz45));
            u64 d67 = add2(add2(mul2(dx67, dx67), mul2(dy67, dy67)), mul2(dz67, dz67));

            float d0, d1, d2, d3, d4, d5, d6, d7;
            unpack2(d0, d1, d01);
            unpack2(d2, d3, d23);
            unpack2(d4, d5, d45);
            unpack2(d6, d7, d67);

            const float m = fminf(fminf(fminf(d0, d1), fminf(d2, d3)),
                                  fminf(fminf(d4, d5), fminf(d6, d7)));

            if (m < best) {   // strict <: earlier groups win ties within segment
                best = m;
                const int jb = segbase + g * 8;
                // First-occurrence within group: descending equality scan.
                int s = jb + 7;
                if (d6 == m) s = jb + 6;
                if (d5 == m) s = jb + 5;
                if (d4 == m) s = jb + 4;
                if (d3 == m) s = jb + 3;
                if (d2 == m) s = jb + 2;
                if (d1 == m) s = jb + 1;
                if (d0 == m) s = jb;
                bi = s;
            }
        }
    }

    // Combine the two segments of each query. Tie -> smaller global index
    // (segments interleave per chunk, so compare indices on exact tie).
    rbest[tid] = best;
    rbi[tid]   = bi;
    __syncthreads();
    if (tid < NQ_BLK) {
        const float ob = rbest[tid + NQ_BLK];
        const int   oi = rbi[tid + NQ_BLK];
        if (ob < best || (ob == best && oi < bi)) { best = ob; bi = oi; }
        outd[(size_t)b * Nq + qi] = best;
        outi[(size_t)b * Nq + qi] = (float)bi;   // <= 8191, exact in fp32
    }
}

extern "C" void kernel_launch(void* const* d_in, const int* in_sizes, int n_in,
                              void* d_out, int out_size)
{
    const float* xyz1 = (const float*)d_in[0];  // [4, 8192, 3]
    const float* xyz2 = (const float*)d_in[1];  // [4, 8192, 3]
    float* out = (float*)d_out;

    const int B = 4;
    const int N = in_sizes[0] / (B * 3);  // 8192
    const int M = in_sizes[1] / (B * 3);  // 8192

    dim3 block(QPB, 1, 1);
    dim3 grid(N / NQ_BLK, B, 2);   // 1024 blocks x 128 threads = 131072 threads
    chamfer_kernel<<<grid, block>>>(xyz1, xyz2, out, N, M, B);
}